// round 5
// baseline (speedup 1.0000x reference)
#include <cuda_runtime.h>
#include <cuda_fp16.h>
#include <cstdint>
#include <cstddef>

#define L_SEQ 512
#define BATCH 128
#define DIM   128
#define HID   512
#define OUTD  5
#define N3H   1536
#define MROWS 65536  // L_SEQ*BATCH

// ---------------- scratch (static device globals; no allocations) ----------------
__device__ __align__(256) __half g_xh[MROWS * DIM];
__device__ __align__(256) __half g_W0t[N3H * DIM];
__device__ __align__(256) __half g_W1t[N3H * HID];
__device__ __align__(256) __half g_U[MROWS * N3H];
__device__ __align__(256) __half g_h1[MROWS * HID];
__device__ __align__(256) float  g_h2last[BATCH * HID];

// ---------------- helpers ----------------
__device__ __forceinline__ uint32_t smem_cast(const void* p)
{
    return (uint32_t)__cvta_generic_to_shared(p);
}

#define CP_ASYNC16(dst, src) asm volatile("cp.async.cg.shared.global [%0], [%1], 16;\n" :: "r"(dst), "l"(src))
#define CP_ASYNC4(dst, src)  asm volatile("cp.async.ca.shared.global [%0], [%1], 4;\n"  :: "r"(dst), "l"(src))
#define CP_COMMIT()          asm volatile("cp.async.commit_group;\n")
#define CP_WAIT1()           asm volatile("cp.async.wait_group 1;\n")
#define CP_WAIT14()          asm volatile("cp.async.wait_group 14;\n")

// ---------------- conversion kernels ----------------
__global__ void f2h_kernel(const float* __restrict__ s, __half* __restrict__ d, int n2)
{
    int i = blockIdx.x * blockDim.x + threadIdx.x;
    if (i < n2) {
        float2 v = reinterpret_cast<const float2*>(s)[i];
        reinterpret_cast<__half2*>(d)[i] = __floats2half2_rn(v.x, v.y);
    }
}

__global__ void trans_f2h_kernel(const float* __restrict__ W, __half* __restrict__ Wt,
                                 int K, int N)
{
    __shared__ float tile[32][33];
    int tx = threadIdx.x;
    int ty = threadIdx.y;
    int nb = blockIdx.x * 32;
    int kb = blockIdx.y * 32;
#pragma unroll
    for (int j = 0; j < 32; j += 8)
        tile[ty + j][tx] = W[(size_t)(kb + ty + j) * N + (nb + tx)];
    __syncthreads();
#pragma unroll
    for (int j = 0; j < 32; j += 8)
        Wt[(size_t)(nb + ty + j) * K + (kb + tx)] = __float2half(tile[tx][ty + j]);
}

// ---------------- GEMM: 256x128 tile, C[m][n] fp16 = A[m][k] * B[n][k]^T ----------------
#define LDSM4(R0, R1, R2, R3, ADDR) \
    asm volatile("ldmatrix.sync.aligned.m8n8.x4.shared.b16 {%0,%1,%2,%3}, [%4];" \
                 : "=r"(R0), "=r"(R1), "=r"(R2), "=r"(R3) : "r"(ADDR))

#define MMA16816(C0, C1, C2, C3, A0, A1, A2, A3, B0, B1)                              \
    asm volatile("mma.sync.aligned.m16n8k16.row.col.f32.f16.f16.f32 "                  \
                 "{%0,%1,%2,%3}, {%4,%5,%6,%7}, {%8,%9}, {%0,%1,%2,%3};"               \
                 : "+f"(C0), "+f"(C1), "+f"(C2), "+f"(C3)                              \
                 : "r"(A0), "r"(A1), "r"(A2), "r"(A3), "r"(B0), "r"(B1))

__device__ __forceinline__ int sw_gran(int row, int seg)
{
    return ((row >> 1) << 3) | ((((row & 1) << 2) | seg) ^ ((row >> 1) & 7));
}

// dynamic smem layout (bytes):
//   A stages: 3 x 16384  at 0
//   B stages: 3 x  8192  at 49152
#define ASTAGE_B 16384
#define BSTAGE_B 8192
#define BBASE_B  49152
#define GSMEM_B  73728

__global__ void __launch_bounds__(256, 1) gemm_kernel(
    const __half* __restrict__ A,   // [M][K]
    const __half* __restrict__ B,   // [N][K]
    __half* __restrict__ C,         // [M][N3H]
    int K)
{
    extern __shared__ __align__(1024) char smem[];

    const int tid  = threadIdx.x;
    const int lane = tid & 31;
    const int wid  = tid >> 5;
    const int wm   = wid & 3;    // 4 warps along M (64 rows each)
    const int wn   = wid >> 2;   // 2 warps along N (64 cols each)
    const int m0   = blockIdx.y * 256;
    const int n0   = blockIdx.x * 128;

    const uint32_t smem_base = smem_cast(smem);

    auto load_tile = [&](int buf, int k0) {
        uint32_t as = smem_base + buf * ASTAGE_B;
        uint32_t bs = smem_base + BBASE_B + buf * BSTAGE_B;
#pragma unroll
        for (int i = 0; i < 4; i++) {          // A: 256 rows x 4 segs
            int lin = tid + i * 256;
            int row = lin >> 2;
            int seg = lin & 3;
            CP_ASYNC16(as + sw_gran(row, seg) * 16,
                       A + (size_t)(m0 + row) * K + (k0 + seg * 8));
        }
#pragma unroll
        for (int i = 0; i < 2; i++) {          // B: 128 rows x 4 segs
            int lin = tid + i * 256;
            int row = lin >> 2;
            int seg = lin & 3;
            CP_ASYNC16(bs + sw_gran(row, seg) * 16,
                       B + (size_t)(n0 + row) * K + (k0 + seg * 8));
        }
    };

    float acc[4][8][4];
#pragma unroll
    for (int mi = 0; mi < 4; mi++)
#pragma unroll
        for (int ni = 0; ni < 8; ni++)
#pragma unroll
            for (int j = 0; j < 4; j++) acc[mi][ni][j] = 0.f;

    const int T = K >> 5;
    load_tile(0, 0);
    CP_COMMIT();
    load_tile(1, 32);
    CP_COMMIT();

    const int a_row_base = wm * 64 + (lane & 15);
    const int a_koff     = lane >> 4;
    const int b_row_base = wn * 64 + (lane & 7) + ((lane & 16) ? 8 : 0);
    const int b_koff     = (lane >> 3) & 1;

    for (int t = 0; t < T; t++) {
        CP_WAIT1();
        __syncthreads();

        if (t + 2 < T) load_tile((t + 2) % 3, (t + 2) << 5);
        CP_COMMIT();

        int cur = t % 3;
        uint32_t as = smem_base + cur * ASTAGE_B;
        uint32_t bs = smem_base + BBASE_B + cur * BSTAGE_B;
#pragma unroll
        for (int kc = 0; kc < 2; kc++) {
            uint32_t a[4][4];
#pragma unroll
            for (int mi = 0; mi < 4; mi++) {
                int row = a_row_base + mi * 16;
                int seg = kc * 2 + a_koff;
                LDSM4(a[mi][0], a[mi][1], a[mi][2], a[mi][3],
                      as + sw_gran(row, seg) * 16);
            }
            uint32_t bf[8][2];
#pragma unroll
            for (int nb = 0; nb < 4; nb++) {
                int row = b_row_base + nb * 16;
                int seg = kc * 2 + b_koff;
                LDSM4(bf[2 * nb][0], bf[2 * nb][1], bf[2 * nb + 1][0], bf[2 * nb + 1][1],
                      bs + sw_gran(row, seg) * 16);
            }
#pragma unroll
            for (int mi = 0; mi < 4; mi++)
#pragma unroll
                for (int ni = 0; ni < 8; ni++)
                    MMA16816(acc[mi][ni][0], acc[mi][ni][1], acc[mi][ni][2], acc[mi][ni][3],
                             a[mi][0], a[mi][1], a[mi][2], a[mi][3],
                             bf[ni][0], bf[ni][1]);
        }
    }

#pragma unroll
    for (int mi = 0; mi < 4; mi++) {
        int m = m0 + wm * 64 + mi * 16 + (lane >> 2);
#pragma unroll
        for (int ni = 0; ni < 8; ni++) {
            int n = n0 + wn * 64 + ni * 8 + (lane & 3) * 2;
            __half2 lo = __floats2half2_rn(acc[mi][ni][0], acc[mi][ni][1]);
            __half2 hi = __floats2half2_rn(acc[mi][ni][2], acc[mi][ni][3]);
            *reinterpret_cast<__half2*>(C + (size_t)m * N3H + n)       = lo;
            *reinterpret_cast<__half2*>(C + (size_t)(m + 8) * N3H + n) = hi;
        }
    }
}

// ---------------- SRU recurrence: per-thread cp.async ring, 32-thread blocks ----------------
#define RSTAGES 16

__device__ __forceinline__ float sigf(float x)
{
    return __fdividef(1.f, 1.f + __expf(-x));
}

__global__ void __launch_bounds__(32) sru_rec_kernel(
    const __half* __restrict__ U,    // [L*B][3H] fp16
    const float* __restrict__ v,
    const float* __restrict__ bb,
    __half* __restrict__ hout,       // [L*B][H] fp16 (store_all)
    float* __restrict__ hlast,       // [B][H] fp32 (!store_all)
    int store_all)
{
    __shared__ __align__(128) __half2 sU[RSTAGES][3][32];   // 6 KB

    const int tid = threadIdx.x;                // 0..31
    const int b   = blockIdx.x >> 3;            // batch
    const int sub = blockIdx.x & 7;
    const int hp  = sub * 32 + tid;             // half2 channel 0..255
    const int h   = hp << 1;

    float2 vf = *reinterpret_cast<const float2*>(v + h);
    float2 vr = *reinterpret_cast<const float2*>(v + HID + h);
    float2 bf = *reinterpret_cast<const float2*>(bb + h);
    float2 br = *reinterpret_cast<const float2*>(bb + HID + h);

    const char* src = (const char*)(U + (size_t)b * N3H + h);
    const size_t step_bytes = (size_t)BATCH * N3H * 2;
    const uint32_t smem0 = smem_cast(&sU[0][0][tid]);

    auto load_stage = [&](int l, int s) {
        const char* p = src + (size_t)l * step_bytes;
        uint32_t d = smem0 + (uint32_t)(s * 384);
        CP_ASYNC4(d,       p);
        CP_ASYNC4(d + 128, p + 1024);   // +HID*2 bytes
        CP_ASYNC4(d + 256, p + 2048);   // +HID*4 bytes
    };

#pragma unroll
    for (int s = 0; s < RSTAGES - 1; s++) {
        load_stage(s, s);
        CP_COMMIT();
    }

    __half2* Hp = reinterpret_cast<__half2*>(hout) + (size_t)b * (HID / 2) + hp;
    const size_t hstep = (size_t)BATCH * (HID / 2);

    float cx = 0.f, cy = 0.f, hx = 0.f, hy = 0.f;

    for (int l = 0; l < L_SEQ; l++) {
        CP_WAIT14();

        int s = l & (RSTAGES - 1);
        float2 u0 = __half22float2(sU[s][0][tid]);
        float2 u1 = __half22float2(sU[s][1][tid]);
        float2 u2 = __half22float2(sU[s][2][tid]);

        int ln = l + RSTAGES - 1;
        if (ln < L_SEQ) load_stage(ln, ln & (RSTAGES - 1));
        CP_COMMIT();

        float fxa = sigf(fmaf(vf.x, cx, u1.x + bf.x));
        float fya = sigf(fmaf(vf.y, cy, u1.y + bf.y));
        float rxa = sigf(fmaf(vr.x, cx, u2.x + br.x));
        float rya = sigf(fmaf(vr.y, cy, u2.y + br.y));

        cx = fmaf(fxa, cx - u0.x, u0.x);
        cy = fmaf(fya, cy - u0.y, u0.y);
        hx = rxa * cx;
        hy = rya * cy;

        if (store_all) Hp[(size_t)l * hstep] = __floats2half2_rn(hx, hy);
    }

    if (!store_all) {
        hlast[b * HID + h]     = hx;
        hlast[b * HID + h + 1] = hy;
    }
}

// ---------------- final FC ----------------
__global__ void fc_kernel(const float* __restrict__ hl, const float* __restrict__ w,
                          const float* __restrict__ bias, float* __restrict__ out)
{
    int o = blockIdx.x;
    int b = blockIdx.y;
    float p = 0.f;
    for (int h = threadIdx.x; h < HID; h += 128)
        p += hl[b * HID + h] * w[o * HID + h];
#pragma unroll
    for (int s = 16; s > 0; s >>= 1) p += __shfl_down_sync(0xffffffffu, p, s);
    __shared__ float red[4];
    if ((threadIdx.x & 31) == 0) red[threadIdx.x >> 5] = p;
    __syncthreads();
    if (threadIdx.x == 0)
        out[b * OUTD + o] = red[0] + red[1] + red[2] + red[3] + bias[o];
}

// ---------------- launch ----------------
extern "C" void kernel_launch(void* const* d_in, const int* in_sizes, int n_in,
                              void* d_out, int out_size)
{
    const float* x   = (const float*)d_in[0];
    const float* W0  = (const float*)d_in[1];
    const float* v0  = (const float*)d_in[2];
    const float* b0  = (const float*)d_in[3];
    const float* W1  = (const float*)d_in[4];
    const float* v1  = (const float*)d_in[5];
    const float* b1  = (const float*)d_in[6];
    const float* fcw = (const float*)d_in[7];
    const float* fcb = (const float*)d_in[8];
    float* out = (float*)d_out;

    void *p_xh, *p_w0t, *p_w1t, *p_u, *p_h1, *p_h2l;
    cudaGetSymbolAddress(&p_xh,  g_xh);
    cudaGetSymbolAddress(&p_w0t, g_W0t);
    cudaGetSymbolAddress(&p_w1t, g_W1t);
    cudaGetSymbolAddress(&p_u,   g_U);
    cudaGetSymbolAddress(&p_h1,  g_h1);
    cudaGetSymbolAddress(&p_h2l, g_h2last);
    __half* xh  = (__half*)p_xh;
    __half* w0t = (__half*)p_w0t;
    __half* w1t = (__half*)p_w1t;
    __half* U   = (__half*)p_u;
    __half* h1  = (__half*)p_h1;
    float*  h2l = (float*)p_h2l;

    static int smem_set = 0;
    if (!smem_set) {
        cudaFuncSetAttribute(gemm_kernel, cudaFuncAttributeMaxDynamicSharedMemorySize, GSMEM_B);
        smem_set = 1;
    }

    const int nx2 = MROWS * DIM / 2;
    f2h_kernel<<<(nx2 + 255) / 256, 256>>>(x, xh, nx2);
    trans_f2h_kernel<<<dim3(N3H / 32, DIM / 32), dim3(32, 8)>>>(W0, w0t, DIM, N3H);
    trans_f2h_kernel<<<dim3(N3H / 32, HID / 32), dim3(32, 8)>>>(W1, w1t, HID, N3H);

    // layer 0
    gemm_kernel<<<dim3(N3H / 128, MROWS / 256), 256, GSMEM_B>>>(xh, w0t, U, DIM);
    sru_rec_kernel<<<BATCH * 8, 32>>>(U, v0, b0, h1, h2l, 1);

    // layer 1
    gemm_kernel<<<dim3(N3H / 128, MROWS / 256), 256, GSMEM_B>>>(h1, w1t, U, HID);
    sru_rec_kernel<<<BATCH * 8, 32>>>(U, v1, b1, h1, h2l, 0);

    // head
    fc_kernel<<<dim3(OUTD, BATCH), 128>>>(h2l, fcw, fcb, out);
}

// round 10
// speedup vs baseline: 1.0320x; 1.0320x over previous
#include <cuda_runtime.h>
#include <cuda_fp16.h>
#include <cstdint>
#include <cstddef>

#define L_SEQ 512
#define BATCH 128
#define DIM   128
#define HID   512
#define OUTD  5
#define N3H   1536
#define MROWS 65536  // L_SEQ*BATCH

// ---------------- scratch (static device globals; no allocations) ----------------
__device__ __align__(256) __half g_xh[MROWS * DIM];
__device__ __align__(256) __half g_W0t[N3H * DIM];
__device__ __align__(256) __half g_W1t[N3H * HID];
__device__ __align__(256) __half g_U[MROWS * N3H];
__device__ __align__(256) __half g_h1[MROWS * HID];
__device__ __align__(256) float  g_h2last[BATCH * HID];
__device__ __align__(256) float  g_bias0[N3H];
__device__ __align__(256) float  g_bias1[N3H];

// ---------------- helpers ----------------
__device__ __forceinline__ uint32_t smem_cast(const void* p)
{
    return (uint32_t)__cvta_generic_to_shared(p);
}

#define CP_ASYNC16(dst, src) asm volatile("cp.async.cg.shared.global [%0], [%1], 16;\n" :: "r"(dst), "l"(src))
#define CP_ASYNC4(dst, src)  asm volatile("cp.async.ca.shared.global [%0], [%1], 4;\n"  :: "r"(dst), "l"(src))
#define CP_COMMIT()          asm volatile("cp.async.commit_group;\n")
#define CP_WAIT1()           asm volatile("cp.async.wait_group 1;\n")
#define CP_WAIT14()          asm volatile("cp.async.wait_group 14;\n")

// ---------------- conversion kernels ----------------
__global__ void f2h_kernel(const float* __restrict__ s, __half* __restrict__ d, int n4)
{
    int i = blockIdx.x * blockDim.x + threadIdx.x;
    if (i < n4) {
        float4 v = reinterpret_cast<const float4*>(s)[i];
        __half2 lo = __floats2half2_rn(v.x, v.y);
        __half2 hi = __floats2half2_rn(v.z, v.w);
        uint2 pkt;
        pkt.x = *reinterpret_cast<uint32_t*>(&lo);
        pkt.y = *reinterpret_cast<uint32_t*>(&hi);
        reinterpret_cast<uint2*>(d)[i] = pkt;
    }
}

__global__ void trans_f2h_kernel(const float* __restrict__ W, __half* __restrict__ Wt,
                                 int K, int N)
{
    __shared__ float tile[32][33];
    int tx = threadIdx.x;
    int ty = threadIdx.y;
    int nb = blockIdx.x * 32;
    int kb = blockIdx.y * 32;
#pragma unroll
    for (int j = 0; j < 32; j += 8)
        tile[ty + j][tx] = W[(size_t)(kb + ty + j) * N + (nb + tx)];
    __syncthreads();
#pragma unroll
    for (int j = 0; j < 32; j += 8)
        Wt[(size_t)(nb + ty + j) * K + (kb + tx)] = __float2half(tile[tx][ty + j]);
}

// bias_full[n] = 0 for n<H (u0), = b[n-H] for n>=H (u1:bf, u2:br)
__global__ void bias_build_kernel(const float* __restrict__ b, float* __restrict__ out)
{
    int i = blockIdx.x * blockDim.x + threadIdx.x;
    if (i < N3H) out[i] = (i < HID) ? 0.f : b[i - HID];
}

// ---------------- common GEMM pieces ----------------
#define LDSM4(R0, R1, R2, R3, ADDR) \
    asm volatile("ldmatrix.sync.aligned.m8n8.x4.shared.b16 {%0,%1,%2,%3}, [%4];" \
                 : "=r"(R0), "=r"(R1), "=r"(R2), "=r"(R3) : "r"(ADDR))

#define MMA16816(C0, C1, C2, C3, A0, A1, A2, A3, B0, B1)                              \
    asm volatile("mma.sync.aligned.m16n8k16.row.col.f32.f16.f16.f32 "                  \
                 "{%0,%1,%2,%3}, {%4,%5,%6,%7}, {%8,%9}, {%0,%1,%2,%3};"               \
                 : "+f"(C0), "+f"(C1), "+f"(C2), "+f"(C3)                              \
                 : "r"(A0), "r"(A1), "r"(A2), "r"(A3), "r"(B0), "r"(B1))

// 16B-granule XOR swizzle: 32-half logical rows, 2 rows share a 128B phys row.
__device__ __forceinline__ int sw_gran(int row, int seg)
{
    return ((row >> 1) << 3) | ((((row & 1) << 2) | seg) ^ ((row >> 1) & 7));
}

// ---------------- GEMM A (layer 1): 128x128 tile, 256 thr, 3-stage (PROVEN) ----------------
__global__ void __launch_bounds__(256, 2) gemm_kernel(
    const __half* __restrict__ A,
    const __half* __restrict__ B,
    const float* __restrict__ bias,
    __half* __restrict__ C,
    int K)
{
    __shared__ __align__(1024) __half As[3][128 * 32];
    __shared__ __align__(1024) __half Bs[3][128 * 32];

    const int tid  = threadIdx.x;
    const int lane = tid & 31;
    const int wid  = tid >> 5;
    const int wm   = wid & 3;
    const int wn   = wid >> 2;
    const int m0   = blockIdx.y * 128;
    const int n0   = blockIdx.x * 128;

    auto load_tile = [&](int buf, int k0) {
        uint32_t as = smem_cast(&As[buf][0]);
        uint32_t bs = smem_cast(&Bs[buf][0]);
#pragma unroll
        for (int i = 0; i < 2; i++) {
            int lin = tid + i * 256;
            int row = lin >> 2;
            int seg = lin & 3;
            int g   = sw_gran(row, seg);
            CP_ASYNC16(as + g * 16, A + (size_t)(m0 + row) * K + (k0 + seg * 8));
            CP_ASYNC16(bs + g * 16, B + (size_t)(n0 + row) * K + (k0 + seg * 8));
        }
    };

    float acc[2][8][4];
#pragma unroll
    for (int mi = 0; mi < 2; mi++)
#pragma unroll
        for (int ni = 0; ni < 8; ni++)
#pragma unroll
            for (int j = 0; j < 4; j++) acc[mi][ni][j] = 0.f;

    const int T = K >> 5;
    load_tile(0, 0);
    CP_COMMIT();
    load_tile(1, 32);
    CP_COMMIT();

    const int a_row_base = wm * 32 + (lane & 15);
    const int a_koff     = lane >> 4;
    const int b_row_base = wn * 64 + (lane & 7) + ((lane & 16) ? 8 : 0);
    const int b_koff     = (lane >> 3) & 1;

    for (int t = 0; t < T; t++) {
        CP_WAIT1();
        __syncthreads();

        if (t + 2 < T) load_tile((t + 2) % 3, (t + 2) << 5);
        CP_COMMIT();

        int cur = t % 3;
        uint32_t as = smem_cast(&As[cur][0]);
        uint32_t bs = smem_cast(&Bs[cur][0]);
#pragma unroll
        for (int kc = 0; kc < 2; kc++) {
            uint32_t a[2][4];
#pragma unroll
            for (int mi = 0; mi < 2; mi++) {
                int row = a_row_base + mi * 16;
                int seg = kc * 2 + a_koff;
                LDSM4(a[mi][0], a[mi][1], a[mi][2], a[mi][3], as + sw_gran(row, seg) * 16);
            }
            uint32_t bf[8][2];
#pragma unroll
            for (int nb = 0; nb < 4; nb++) {
                int row = b_row_base + nb * 16;
                int seg = kc * 2 + b_koff;
                LDSM4(bf[2 * nb][0], bf[2 * nb][1], bf[2 * nb + 1][0], bf[2 * nb + 1][1],
                      bs + sw_gran(row, seg) * 16);
            }
#pragma unroll
            for (int mi = 0; mi < 2; mi++)
#pragma unroll
                for (int ni = 0; ni < 8; ni++)
                    MMA16816(acc[mi][ni][0], acc[mi][ni][1], acc[mi][ni][2], acc[mi][ni][3],
                             a[mi][0], a[mi][1], a[mi][2], a[mi][3],
                             bf[ni][0], bf[ni][1]);
        }
        __syncthreads();
    }

#pragma unroll
    for (int mi = 0; mi < 2; mi++) {
        int m = m0 + wm * 32 + mi * 16 + (lane >> 2);
#pragma unroll
        for (int ni = 0; ni < 8; ni++) {
            int n = n0 + wn * 64 + ni * 8 + (lane & 3) * 2;
            float2 bb = *reinterpret_cast<const float2*>(bias + n);
            __half2 lo = __floats2half2_rn(acc[mi][ni][0] + bb.x, acc[mi][ni][1] + bb.y);
            __half2 hi = __floats2half2_rn(acc[mi][ni][2] + bb.x, acc[mi][ni][3] + bb.y);
            *reinterpret_cast<__half2*>(C + (size_t)m * N3H + n)       = lo;
            *reinterpret_cast<__half2*>(C + (size_t)(m + 8) * N3H + n) = hi;
        }
    }
}

// ---------------- GEMM B (layer 0): 128x256 tile, 512 thr, 3-stage ----------------
// A re-read drops from 12x to 6x. 16 warps/SM (1 CTA), same warp count as gemm_kernel@2CTA.
#define WA_STAGE 8192    // 128 rows x 32 halfs
#define WB_STAGE 16384   // 256 rows x 32 halfs
#define WB_BASE  (3 * WA_STAGE)
#define WSMEM_B  (3 * (WA_STAGE + WB_STAGE))   // 73728

__global__ void __launch_bounds__(512, 1) gemm_wide_kernel(
    const __half* __restrict__ A,
    const __half* __restrict__ B,
    const float* __restrict__ bias,
    __half* __restrict__ C,
    int K)
{
    extern __shared__ __align__(1024) char wsmem[];

    const int tid  = threadIdx.x;
    const int lane = tid & 31;
    const int wid  = tid >> 5;
    const int wm   = wid & 3;    // 4 warps along M (32 rows)
    const int wn   = wid >> 2;   // 4 warps along N (64 cols)
    const int m0   = blockIdx.y * 128;
    const int n0   = blockIdx.x * 256;

    const uint32_t sb = smem_cast(wsmem);

    auto load_tile = [&](int buf, int k0) {
        uint32_t as = sb + buf * WA_STAGE;
        uint32_t bs = sb + WB_BASE + buf * WB_STAGE;
        {   // A: 512 granules, 1 per thread
            int row = tid >> 2;
            int seg = tid & 3;
            CP_ASYNC16(as + sw_gran(row, seg) * 16, A + (size_t)(m0 + row) * K + (k0 + seg * 8));
        }
#pragma unroll
        for (int i = 0; i < 2; i++) {   // B: 1024 granules
            int lin = tid + i * 512;
            int row = lin >> 2;
            int seg = lin & 3;
            CP_ASYNC16(bs + sw_gran(row, seg) * 16, B + (size_t)(n0 + row) * K + (k0 + seg * 8));
        }
    };

    float acc[2][8][4];
#pragma unroll
    for (int mi = 0; mi < 2; mi++)
#pragma unroll
        for (int ni = 0; ni < 8; ni++)
#pragma unroll
            for (int j = 0; j < 4; j++) acc[mi][ni][j] = 0.f;

    const int T = K >> 5;
    load_tile(0, 0);
    CP_COMMIT();
    load_tile(1, 32);
    CP_COMMIT();

    const int a_row_base = wm * 32 + (lane & 15);
    const int a_koff     = lane >> 4;
    const int b_row_base = wn * 64 + (lane & 7) + ((lane & 16) ? 8 : 0);
    const int b_koff     = (lane >> 3) & 1;

    for (int t = 0; t < T; t++) {
        CP_WAIT1();
        __syncthreads();

        if (t + 2 < T) load_tile((t + 2) % 3, (t + 2) << 5);
        CP_COMMIT();

        int cur = t % 3;
        uint32_t as = sb + cur * WA_STAGE;
        uint32_t bs = sb + WB_BASE + cur * WB_STAGE;
#pragma unroll
        for (int kc = 0; kc < 2; kc++) {
            uint32_t a[2][4];
#pragma unroll
            for (int mi = 0; mi < 2; mi++) {
                int row = a_row_base + mi * 16;
                int seg = kc * 2 + a_koff;
                LDSM4(a[mi][0], a[mi][1], a[mi][2], a[mi][3], as + sw_gran(row, seg) * 16);
            }
            uint32_t bf[8][2];
#pragma unroll
            for (int nb = 0; nb < 4; nb++) {
                int row = b_row_base + nb * 16;
                int seg = kc * 2 + b_koff;
                LDSM4(bf[2 * nb][0], bf[2 * nb][1], bf[2 * nb + 1][0], bf[2 * nb + 1][1],
                      bs + sw_gran(row, seg) * 16);
            }
#pragma unroll
            for (int mi = 0; mi < 2; mi++)
#pragma unroll
                for (int ni = 0; ni < 8; ni++)
                    MMA16816(acc[mi][ni][0], acc[mi][ni][1], acc[mi][ni][2], acc[mi][ni][3],
                             a[mi][0], a[mi][1], a[mi][2], a[mi][3],
                             bf[ni][0], bf[ni][1]);
        }
        __syncthreads();
    }

#pragma unroll
    for (int mi = 0; mi < 2; mi++) {
        int m = m0 + wm * 32 + mi * 16 + (lane >> 2);
#pragma unroll
        for (int ni = 0; ni < 8; ni++) {
            int n = n0 + wn * 64 + ni * 8 + (lane & 3) * 2;
            float2 bb = *reinterpret_cast<const float2*>(bias + n);
            __half2 lo = __floats2half2_rn(acc[mi][ni][0] + bb.x, acc[mi][ni][1] + bb.y);
            __half2 hi = __floats2half2_rn(acc[mi][ni][2] + bb.x, acc[mi][ni][3] + bb.y);
            *reinterpret_cast<__half2*>(C + (size_t)m * N3H + n)       = lo;
            *reinterpret_cast<__half2*>(C + (size_t)(m + 8) * N3H + n) = hi;
        }
    }
}

// ---------------- SRU recurrence: per-thread cp.async ring (bias pre-folded in U) ----------------
#define RSTAGES 16

__device__ __forceinline__ float sigf(float x)
{
    return __fdividef(1.f, 1.f + __expf(-x));
}

__global__ void __launch_bounds__(32) sru_rec_kernel(
    const __half* __restrict__ U,    // [L*B][3H] fp16, u1/u2 already include biases
    const float* __restrict__ v,
    __half* __restrict__ hout,       // [L*B][H] fp16 (store_all)
    float* __restrict__ hlast,       // [B][H] fp32 (!store_all)
    int store_all)
{
    __shared__ __align__(128) __half2 sU[RSTAGES][3][32];   // 6 KB

    const int tid = threadIdx.x;
    const int b   = blockIdx.x >> 3;
    const int sub = blockIdx.x & 7;
    const int hp  = sub * 32 + tid;
    const int h   = hp << 1;

    float2 vf = *reinterpret_cast<const float2*>(v + h);
    float2 vr = *reinterpret_cast<const float2*>(v + HID + h);

    const char* src = (const char*)(U + (size_t)b * N3H + h);
    const size_t step_bytes = (size_t)BATCH * N3H * 2;
    const uint32_t smem0 = smem_cast(&sU[0][0][tid]);

    auto load_stage = [&](int l, int s) {
        const char* p = src + (size_t)l * step_bytes;
        uint32_t d = smem0 + (uint32_t)(s * 384);
        CP_ASYNC4(d,       p);
        CP_ASYNC4(d + 128, p + 1024);
        CP_ASYNC4(d + 256, p + 2048);
    };

#pragma unroll
    for (int s = 0; s < RSTAGES - 1; s++) {
        load_stage(s, s);
        CP_COMMIT();
    }

    __half2* Hp = reinterpret_cast<__half2*>(hout) + (size_t)b * (HID / 2) + hp;
    const size_t hstep = (size_t)BATCH * (HID / 2);

    float cx = 0.f, cy = 0.f, hx = 0.f, hy = 0.f;

    for (int l = 0; l < L_SEQ; l++) {
        CP_WAIT14();

        int s = l & (RSTAGES - 1);
        float2 u0 = __half22float2(sU[s][0][tid]);
        float2 u1 = __half22float2(sU[s][1][tid]);
        float2 u2 = __half22float2(sU[s][2][tid]);

        int ln = l + RSTAGES - 1;
        if (ln < L_SEQ) load_stage(ln, ln & (RSTAGES - 1));
        CP_COMMIT();

        float fxa = sigf(fmaf(vf.x, cx, u1.x));
        float fya = sigf(fmaf(vf.y, cy, u1.y));
        float rxa = sigf(fmaf(vr.x, cx, u2.x));
        float rya = sigf(fmaf(vr.y, cy, u2.y));

        cx = fmaf(fxa, cx - u0.x, u0.x);
        cy = fmaf(fya, cy - u0.y, u0.y);
        hx = rxa * cx;
        hy = rya * cy;

        if (store_all) Hp[(size_t)l * hstep] = __floats2half2_rn(hx, hy);
    }

    if (!store_all) {
        hlast[b * HID + h]     = hx;
        hlast[b * HID + h + 1] = hy;
    }
}

// ---------------- final FC ----------------
__global__ void fc_kernel(const float* __restrict__ hl, const float* __restrict__ w,
                          const float* __restrict__ bias, float* __restrict__ out)
{
    int o = blockIdx.x;
    int b = blockIdx.y;
    float p = 0.f;
    for (int h = threadIdx.x; h < HID; h += 128)
        p += hl[b * HID + h] * w[o * HID + h];
#pragma unroll
    for (int s = 16; s > 0; s >>= 1) p += __shfl_down_sync(0xffffffffu, p, s);
    __shared__ float red[4];
    if ((threadIdx.x & 31) == 0) red[threadIdx.x >> 5] = p;
    __syncthreads();
    if (threadIdx.x == 0)
        out[b * OUTD + o] = red[0] + red[1] + red[2] + red[3] + bias[o];
}

// ---------------- launch ----------------
extern "C" void kernel_launch(void* const* d_in, const int* in_sizes, int n_in,
                              void* d_out, int out_size)
{
    const float* x   = (const float*)d_in[0];
    const float* W0  = (const float*)d_in[1];
    const float* v0  = (const float*)d_in[2];
    const float* b0  = (const float*)d_in[3];
    const float* W1  = (const float*)d_in[4];
    const float* v1  = (const float*)d_in[5];
    const float* b1  = (const float*)d_in[6];
    const float* fcw = (const float*)d_in[7];
    const float* fcb = (const float*)d_in[8];
    float* out = (float*)d_out;

    void *p_xh, *p_w0t, *p_w1t, *p_u, *p_h1, *p_h2l, *p_bi0, *p_bi1;
    cudaGetSymbolAddress(&p_xh,  g_xh);
    cudaGetSymbolAddress(&p_w0t, g_W0t);
    cudaGetSymbolAddress(&p_w1t, g_W1t);
    cudaGetSymbolAddress(&p_u,   g_U);
    cudaGetSymbolAddress(&p_h1,  g_h1);
    cudaGetSymbolAddress(&p_h2l, g_h2last);
    cudaGetSymbolAddress(&p_bi0, g_bias0);
    cudaGetSymbolAddress(&p_bi1, g_bias1);
    __half* xh  = (__half*)p_xh;
    __half* w0t = (__half*)p_w0t;
    __half* w1t = (__half*)p_w1t;
    __half* U   = (__half*)p_u;
    __half* h1  = (__half*)p_h1;
    float*  h2l = (float*)p_h2l;
    float*  bi0 = (float*)p_bi0;
    float*  bi1 = (float*)p_bi1;

    static int smem_set = 0;
    if (!smem_set) {
        cudaFuncSetAttribute(gemm_wide_kernel, cudaFuncAttributeMaxDynamicSharedMemorySize, WSMEM_B);
        smem_set = 1;
    }

    const int nx4 = MROWS * DIM / 4;
    f2h_kernel<<<(nx4 + 255) / 256, 256>>>(x, xh, nx4);
    trans_f2h_kernel<<<dim3(N3H / 32, DIM / 32), dim3(32, 8)>>>(W0, w0t, DIM, N3H);
    trans_f2h_kernel<<<dim3(N3H / 32, HID / 32), dim3(32, 8)>>>(W1, w1t, HID, N3H);
    bias_build_kernel<<<(N3H + 255) / 256, 256>>>(b0, bi0);
    bias_build_kernel<<<(N3H + 255) / 256, 256>>>(b1, bi1);

    // layer 0: wide tile (A re-read 6x instead of 12x)
    gemm_wide_kernel<<<dim3(N3H / 256, MROWS / 128), 512, WSMEM_B>>>(xh, w0t, bi0, U, DIM);
    sru_rec_kernel<<<BATCH * 8, 32>>>(U, v0, h1, h2l, 1);

    // layer 1: proven 128x128 kernel (near HMMA peak)
    gemm_kernel<<<dim3(N3H / 128, MROWS / 128), 256>>>(h1, w1t, bi1, U, HID);
    sru_rec_kernel<<<BATCH * 8, 32>>>(U, v1, h1, h2l, 0);

    // head
    fc_kernel<<<dim3(OUTD, BATCH), 128>>>(h2l, fcw, fcb, out);
}

// round 11
// speedup vs baseline: 1.1030x; 1.0688x over previous
#include <cuda_runtime.h>
#include <cuda_fp16.h>
#include <cstdint>
#include <cstddef>

#define L_SEQ 512
#define BATCH 128
#define DIM   128
#define HID   512
#define OUTD  5
#define N3H   1536
#define MROWS 65536  // L_SEQ*BATCH

// ---------------- scratch (static device globals; no allocations) ----------------
__device__ __align__(256) __half g_xh[MROWS * DIM];
__device__ __align__(256) __half g_W0t[N3H * DIM];
__device__ __align__(256) __half g_W1t[N3H * HID];
__device__ __align__(256) __half g_U[MROWS * N3H];
__device__ __align__(256) __half g_h1[MROWS * HID];
__device__ __align__(256) float  g_h2last[BATCH * HID];
__device__ __align__(256) float  g_bias0[N3H];
__device__ __align__(256) float  g_bias1[N3H];

// ---------------- helpers ----------------
__device__ __forceinline__ uint32_t smem_cast(const void* p)
{
    return (uint32_t)__cvta_generic_to_shared(p);
}

#define CP_ASYNC16(dst, src) asm volatile("cp.async.cg.shared.global [%0], [%1], 16;\n" :: "r"(dst), "l"(src))
#define CP_ASYNC4(dst, src)  asm volatile("cp.async.ca.shared.global [%0], [%1], 4;\n"  :: "r"(dst), "l"(src))
#define CP_COMMIT()          asm volatile("cp.async.commit_group;\n")
#define CP_WAIT1()           asm volatile("cp.async.wait_group 1;\n")
#define CP_WAIT14()          asm volatile("cp.async.wait_group 14;\n")

__device__ __forceinline__ float tanh_approx(float x)
{
    float t;
    asm("tanh.approx.f32 %0, %1;" : "=f"(t) : "f"(x));
    return t;
}

// ---------------- conversion kernels ----------------
__global__ void f2h_kernel(const float* __restrict__ s, __half* __restrict__ d, int n4)
{
    int i = blockIdx.x * blockDim.x + threadIdx.x;
    if (i < n4) {
        float4 v = reinterpret_cast<const float4*>(s)[i];
        __half2 lo = __floats2half2_rn(v.x, v.y);
        __half2 hi = __floats2half2_rn(v.z, v.w);
        uint2 pkt;
        pkt.x = *reinterpret_cast<uint32_t*>(&lo);
        pkt.y = *reinterpret_cast<uint32_t*>(&hi);
        reinterpret_cast<uint2*>(d)[i] = pkt;
    }
}

__global__ void trans_f2h_kernel(const float* __restrict__ W, __half* __restrict__ Wt,
                                 int K, int N)
{
    __shared__ float tile[32][33];
    int tx = threadIdx.x;
    int ty = threadIdx.y;
    int nb = blockIdx.x * 32;
    int kb = blockIdx.y * 32;
#pragma unroll
    for (int j = 0; j < 32; j += 8)
        tile[ty + j][tx] = W[(size_t)(kb + ty + j) * N + (nb + tx)];
    __syncthreads();
#pragma unroll
    for (int j = 0; j < 32; j += 8)
        Wt[(size_t)(nb + ty + j) * K + (kb + tx)] = __float2half(tile[tx][ty + j]);
}

// bias_half[n] = 0 for n<H (u0 cols), = 0.5*b[n-H] for n>=H (u1/u2 cols, pre-scaled
// for the tanh-form sigmoid; the GEMM epilogue also scales acc by 0.5 on those cols)
__global__ void bias_build_kernel(const float* __restrict__ b, float* __restrict__ out)
{
    int i = blockIdx.x * blockDim.x + threadIdx.x;
    if (i < N3H) out[i] = (i < HID) ? 0.f : 0.5f * b[i - HID];
}

// ---------------- GEMM: 128x128 tile, 256 thr, 3-stage (PROVEN config) ----------------
#define LDSM4(R0, R1, R2, R3, ADDR) \
    asm volatile("ldmatrix.sync.aligned.m8n8.x4.shared.b16 {%0,%1,%2,%3}, [%4];" \
                 : "=r"(R0), "=r"(R1), "=r"(R2), "=r"(R3) : "r"(ADDR))

#define MMA16816(C0, C1, C2, C3, A0, A1, A2, A3, B0, B1)                              \
    asm volatile("mma.sync.aligned.m16n8k16.row.col.f32.f16.f16.f32 "                  \
                 "{%0,%1,%2,%3}, {%4,%5,%6,%7}, {%8,%9}, {%0,%1,%2,%3};"               \
                 : "+f"(C0), "+f"(C1), "+f"(C2), "+f"(C3)                              \
                 : "r"(A0), "r"(A1), "r"(A2), "r"(A3), "r"(B0), "r"(B1))

__device__ __forceinline__ int sw_gran(int row, int seg)
{
    return ((row >> 1) << 3) | ((((row & 1) << 2) | seg) ^ ((row >> 1) & 7));
}

__global__ void __launch_bounds__(256, 2) gemm_kernel(
    const __half* __restrict__ A,
    const __half* __restrict__ B,
    const float* __restrict__ bias,   // pre-scaled: 0 | 0.5*b
    __half* __restrict__ C,
    int K)
{
    __shared__ __align__(1024) __half As[3][128 * 32];
    __shared__ __align__(1024) __half Bs[3][128 * 32];

    const int tid  = threadIdx.x;
    const int lane = tid & 31;
    const int wid  = tid >> 5;
    const int wm   = wid & 3;
    const int wn   = wid >> 2;
    const int m0   = blockIdx.y * 128;
    const int n0   = blockIdx.x * 128;
    // HID is a multiple of the 128-wide N tile -> scale uniform per CTA column
    const float s  = (n0 < HID) ? 1.f : 0.5f;

    auto load_tile = [&](int buf, int k0) {
        uint32_t as = smem_cast(&As[buf][0]);
        uint32_t bs = smem_cast(&Bs[buf][0]);
#pragma unroll
        for (int i = 0; i < 2; i++) {
            int lin = tid + i * 256;
            int row = lin >> 2;
            int seg = lin & 3;
            int g   = sw_gran(row, seg);
            CP_ASYNC16(as + g * 16, A + (size_t)(m0 + row) * K + (k0 + seg * 8));
            CP_ASYNC16(bs + g * 16, B + (size_t)(n0 + row) * K + (k0 + seg * 8));
        }
    };

    float acc[2][8][4];
#pragma unroll
    for (int mi = 0; mi < 2; mi++)
#pragma unroll
        for (int ni = 0; ni < 8; ni++)
#pragma unroll
            for (int j = 0; j < 4; j++) acc[mi][ni][j] = 0.f;

    const int T = K >> 5;
    load_tile(0, 0);
    CP_COMMIT();
    load_tile(1, 32);
    CP_COMMIT();

    const int a_row_base = wm * 32 + (lane & 15);
    const int a_koff     = lane >> 4;
    const int b_row_base = wn * 64 + (lane & 7) + ((lane & 16) ? 8 : 0);
    const int b_koff     = (lane >> 3) & 1;

    for (int t = 0; t < T; t++) {
        CP_WAIT1();
        __syncthreads();

        if (t + 2 < T) load_tile((t + 2) % 3, (t + 2) << 5);
        CP_COMMIT();

        int cur = t % 3;
        uint32_t as = smem_cast(&As[cur][0]);
        uint32_t bs = smem_cast(&Bs[cur][0]);
#pragma unroll
        for (int kc = 0; kc < 2; kc++) {
            uint32_t a[2][4];
#pragma unroll
            for (int mi = 0; mi < 2; mi++) {
                int row = a_row_base + mi * 16;
                int seg = kc * 2 + a_koff;
                LDSM4(a[mi][0], a[mi][1], a[mi][2], a[mi][3], as + sw_gran(row, seg) * 16);
            }
            uint32_t bf[8][2];
#pragma unroll
            for (int nb = 0; nb < 4; nb++) {
                int row = b_row_base + nb * 16;
                int seg = kc * 2 + b_koff;
                LDSM4(bf[2 * nb][0], bf[2 * nb][1], bf[2 * nb + 1][0], bf[2 * nb + 1][1],
                      bs + sw_gran(row, seg) * 16);
            }
#pragma unroll
            for (int mi = 0; mi < 2; mi++)
#pragma unroll
                for (int ni = 0; ni < 8; ni++)
                    MMA16816(acc[mi][ni][0], acc[mi][ni][1], acc[mi][ni][2], acc[mi][ni][3],
                             a[mi][0], a[mi][1], a[mi][2], a[mi][3],
                             bf[ni][0], bf[ni][1]);
        }
        __syncthreads();
    }

#pragma unroll
    for (int mi = 0; mi < 2; mi++) {
        int m = m0 + wm * 32 + mi * 16 + (lane >> 2);
#pragma unroll
        for (int ni = 0; ni < 8; ni++) {
            int n = n0 + wn * 64 + ni * 8 + (lane & 3) * 2;
            float2 bb = *reinterpret_cast<const float2*>(bias + n);
            __half2 lo = __floats2half2_rn(fmaf(acc[mi][ni][0], s, bb.x),
                                           fmaf(acc[mi][ni][1], s, bb.y));
            __half2 hi = __floats2half2_rn(fmaf(acc[mi][ni][2], s, bb.x),
                                           fmaf(acc[mi][ni][3], s, bb.y));
            *reinterpret_cast<__half2*>(C + (size_t)m * N3H + n)       = lo;
            *reinterpret_cast<__half2*>(C + (size_t)(m + 8) * N3H + n) = hi;
        }
    }
}

// ---------------- SRU recurrence: tanh.approx sigmoid, per-thread cp.async ring ----------------
// U layout per step: u0 raw; u1 = 0.5*(u1_gemm + bf); u2 = 0.5*(u2_gemm + br).
// sigmoid(z) = 0.5 + 0.5*tanh(z/2); z/2 = vf_half*c + u1  (vf_half = 0.5*vf).
#define RSTAGES 16

__global__ void __launch_bounds__(32) sru_rec_kernel(
    const __half* __restrict__ U,
    const float* __restrict__ v,
    __half* __restrict__ hout,       // [L*B][H] fp16 (store_all)
    float* __restrict__ hlast,       // [B][H] fp32 (!store_all)
    int store_all)
{
    __shared__ __align__(128) __half2 sU[RSTAGES][3][32];   // 6 KB

    const int tid = threadIdx.x;
    const int b   = blockIdx.x >> 3;
    const int sub = blockIdx.x & 7;
    const int hp  = sub * 32 + tid;
    const int h   = hp << 1;

    float2 vf = *reinterpret_cast<const float2*>(v + h);
    float2 vr = *reinterpret_cast<const float2*>(v + HID + h);
    vf.x *= 0.5f; vf.y *= 0.5f;
    vr.x *= 0.5f; vr.y *= 0.5f;

    const char* src = (const char*)(U + (size_t)b * N3H + h);
    const size_t step_bytes = (size_t)BATCH * N3H * 2;
    const uint32_t smem0 = smem_cast(&sU[0][0][tid]);

    auto load_stage = [&](int l, int s) {
        const char* p = src + (size_t)l * step_bytes;
        uint32_t d = smem0 + (uint32_t)(s * 384);
        CP_ASYNC4(d,       p);
        CP_ASYNC4(d + 128, p + 1024);
        CP_ASYNC4(d + 256, p + 2048);
    };

#pragma unroll
    for (int s = 0; s < RSTAGES - 1; s++) {
        load_stage(s, s);
        CP_COMMIT();
    }

    __half2* Hp = reinterpret_cast<__half2*>(hout) + (size_t)b * (HID / 2) + hp;
    const size_t hstep = (size_t)BATCH * (HID / 2);

    float cx = 0.f, cy = 0.f, hx = 0.f, hy = 0.f;

    for (int l = 0; l < L_SEQ; l++) {
        CP_WAIT14();

        int s = l & (RSTAGES - 1);
        float2 u0 = __half22float2(sU[s][0][tid]);
        float2 u1 = __half22float2(sU[s][1][tid]);
        float2 u2 = __half22float2(sU[s][2][tid]);

        int ln = l + RSTAGES - 1;
        if (ln < L_SEQ) load_stage(ln, ln & (RSTAGES - 1));
        CP_COMMIT();

        float tfx = tanh_approx(fmaf(vf.x, cx, u1.x));
        float tfy = tanh_approx(fmaf(vf.y, cy, u1.y));
        float trx = tanh_approx(fmaf(vr.x, cx, u2.x));
        float try_ = tanh_approx(fmaf(vr.y, cy, u2.y));

        float fx = fmaf(tfx, 0.5f, 0.5f);
        float fy = fmaf(tfy, 0.5f, 0.5f);
        float rx = fmaf(trx, 0.5f, 0.5f);
        float ry = fmaf(try_, 0.5f, 0.5f);

        cx = fmaf(fx, cx - u0.x, u0.x);
        cy = fmaf(fy, cy - u0.y, u0.y);
        hx = rx * cx;
        hy = ry * cy;

        if (store_all) Hp[(size_t)l * hstep] = __floats2half2_rn(hx, hy);
    }

    if (!store_all) {
        hlast[b * HID + h]     = hx;
        hlast[b * HID + h + 1] = hy;
    }
}

// ---------------- final FC ----------------
__global__ void fc_kernel(const float* __restrict__ hl, const float* __restrict__ w,
                          const float* __restrict__ bias, float* __restrict__ out)
{
    int o = blockIdx.x;
    int b = blockIdx.y;
    float p = 0.f;
    for (int h = threadIdx.x; h < HID; h += 128)
        p += hl[b * HID + h] * w[o * HID + h];
#pragma unroll
    for (int s = 16; s > 0; s >>= 1) p += __shfl_down_sync(0xffffffffu, p, s);
    __shared__ float red[4];
    if ((threadIdx.x & 31) == 0) red[threadIdx.x >> 5] = p;
    __syncthreads();
    if (threadIdx.x == 0)
        out[b * OUTD + o] = red[0] + red[1] + red[2] + red[3] + bias[o];
}

// ---------------- launch ----------------
extern "C" void kernel_launch(void* const* d_in, const int* in_sizes, int n_in,
                              void* d_out, int out_size)
{
    const float* x   = (const float*)d_in[0];
    const float* W0  = (const float*)d_in[1];
    const float* v0  = (const float*)d_in[2];
    const float* b0  = (const float*)d_in[3];
    const float* W1  = (const float*)d_in[4];
    const float* v1  = (const float*)d_in[5];
    const float* b1  = (const float*)d_in[6];
    const float* fcw = (const float*)d_in[7];
    const float* fcb = (const float*)d_in[8];
    float* out = (float*)d_out;

    void *p_xh, *p_w0t, *p_w1t, *p_u, *p_h1, *p_h2l, *p_bi0, *p_bi1;
    cudaGetSymbolAddress(&p_xh,  g_xh);
    cudaGetSymbolAddress(&p_w0t, g_W0t);
    cudaGetSymbolAddress(&p_w1t, g_W1t);
    cudaGetSymbolAddress(&p_u,   g_U);
    cudaGetSymbolAddress(&p_h1,  g_h1);
    cudaGetSymbolAddress(&p_h2l, g_h2last);
    cudaGetSymbolAddress(&p_bi0, g_bias0);
    cudaGetSymbolAddress(&p_bi1, g_bias1);
    __half* xh  = (__half*)p_xh;
    __half* w0t = (__half*)p_w0t;
    __half* w1t = (__half*)p_w1t;
    __half* U   = (__half*)p_u;
    __half* h1  = (__half*)p_h1;
    float*  h2l = (float*)p_h2l;
    float*  bi0 = (float*)p_bi0;
    float*  bi1 = (float*)p_bi1;

    const int nx4 = MROWS * DIM / 4;
    f2h_kernel<<<(nx4 + 255) / 256, 256>>>(x, xh, nx4);                               // 0
    trans_f2h_kernel<<<dim3(N3H / 32, DIM / 32), dim3(32, 8)>>>(W0, w0t, DIM, N3H);   // 1
    trans_f2h_kernel<<<dim3(N3H / 32, HID / 32), dim3(32, 8)>>>(W1, w1t, HID, N3H);   // 2
    bias_build_kernel<<<(N3H + 255) / 256, 256>>>(b0, bi0);                           // 3

    // layer 0
    gemm_kernel<<<dim3(N3H / 128, MROWS / 128), 256>>>(xh, w0t, bi0, U, DIM);         // 4
    sru_rec_kernel<<<BATCH * 8, 32>>>(U, v0, h1, h2l, 1);                             // 5 <- ncu -s 5
    bias_build_kernel<<<(N3H + 255) / 256, 256>>>(b1, bi1);                           // 6

    // layer 1
    gemm_kernel<<<dim3(N3H / 128, MROWS / 128), 256>>>(h1, w1t, bi1, U, HID);         // 7
    sru_rec_kernel<<<BATCH * 8, 32>>>(U, v1, h1, h2l, 0);                             // 8

    // head
    fc_kernel<<<dim3(OUTD, BATCH), 128>>>(h2l, fcw, fcb, out);                        // 9
}